// round 17
// baseline (speedup 1.0000x reference)
#include <cuda_runtime.h>
#include <cuda_fp16.h>
#include <cstdint>

#define Bb 2
#define Ss 2048
#define Dd 512
#define Hh 8
#define HDIM 64
#define SCALE 0.125f

// ---------------------------------------------------------------------------
// Device-global scratch (single fp16 planes)
// ---------------------------------------------------------------------------
__device__ uint16_t g_gene_h[Bb*Ss*Dd];
__device__ uint16_t g_expr_h[Bb*Ss*Dd];
__device__ uint16_t g_fus_h[Bb*Ss*Dd];
__device__ uint16_t g_q_h[Bb*Ss*Dd];
__device__ uint16_t g_k_h[Bb*Ss*Dd];
__device__ uint16_t g_v_h[Bb*Ss*Dd];
__device__ uint16_t g_at_h[Bb*Ss*Dd];
__device__ uint16_t g_wtf_h[Dd*2*Dd];                         // [512][1024]
__device__ uint16_t g_wtqkv_h[3*Dd*Dd];                       // [1536][512] Q,K,V rows
__device__ uint16_t g_wto_h[Dd*Dd];
__device__ uint32_t g_mbits[Bb*Ss*(Ss/32)];

// ---------------------------------------------------------------------------
// Helpers
// ---------------------------------------------------------------------------
__device__ __forceinline__ uint32_t smem_u32(const void* p) {
    return (uint32_t)__cvta_generic_to_shared(p);
}
__device__ __forceinline__ uint32_t pack2h(float x, float y) {
    __half2 h = __floats2half2_rn(x, y);
    return reinterpret_cast<uint32_t&>(h);
}
__device__ __forceinline__ void mma16816(float c[4], const uint32_t* a, const uint32_t* b) {
    asm volatile(
        "mma.sync.aligned.m16n8k16.row.col.f32.f16.f16.f32 "
        "{%0,%1,%2,%3}, {%4,%5,%6,%7}, {%8,%9}, {%0,%1,%2,%3};\n"
        : "+f"(c[0]), "+f"(c[1]), "+f"(c[2]), "+f"(c[3])
        : "r"(a[0]), "r"(a[1]), "r"(a[2]), "r"(a[3]), "r"(b[0]), "r"(b[1]));
}
__device__ __forceinline__ void ldsm_x4(uint32_t a[4], uint32_t addr) {
    asm volatile("ldmatrix.sync.aligned.m8n8.x4.shared.b16 {%0,%1,%2,%3}, [%4];"
        : "=r"(a[0]), "=r"(a[1]), "=r"(a[2]), "=r"(a[3]) : "r"(addr));
}
__device__ __forceinline__ void ldsm_x4_t(uint32_t a[4], uint32_t addr) {
    asm volatile("ldmatrix.sync.aligned.m8n8.x4.trans.shared.b16 {%0,%1,%2,%3}, [%4];"
        : "=r"(a[0]), "=r"(a[1]), "=r"(a[2]), "=r"(a[3]) : "r"(addr));
}
__device__ __forceinline__ void cpa16(uint32_t dst, const void* src) {
    asm volatile("cp.async.cg.shared.global [%0], [%1], 16;" :: "r"(dst), "l"(src));
}
__device__ __forceinline__ void cpa_commit() { asm volatile("cp.async.commit_group;"); }
template<int N> __device__ __forceinline__ void cpa_wait() {
    asm volatile("cp.async.wait_group %0;" :: "n"(N) : "memory");
}

// ---------------------------------------------------------------------------
// Pre-pass kernels (unchanged)
// ---------------------------------------------------------------------------
__global__ __launch_bounds__(256) void maskbits_kernel(const float* __restrict__ M,
                                                       uint32_t* __restrict__ bits) {
    int idx = blockIdx.x * 256 + threadIdx.x;
    float v = M[idx];
    uint32_t b = __ballot_sync(0xffffffffu, v != 0.f);
    if ((threadIdx.x & 31) == 0) bits[idx >> 5] = b;
}

__global__ __launch_bounds__(256) void conv_kernel(
    const float* __restrict__ in0, uint16_t* __restrict__ out0,
    const float* __restrict__ in1, uint16_t* __restrict__ out1)
{
    const float* in = blockIdx.y ? in1 : in0;
    uint16_t* outp = blockIdx.y ? out1 : out0;
    int i = (blockIdx.x * 256 + threadIdx.x) * 4;
    float4 v = *(const float4*)(in + i);
    *(uint2*)(outp + i) = make_uint2(pack2h(v.x, v.y), pack2h(v.z, v.w));
}

__global__ __launch_bounds__(256) void transpose_all_kernel(
    const float* __restrict__ Wf, const float* __restrict__ Wq,
    const float* __restrict__ Wk, const float* __restrict__ Wv,
    const float* __restrict__ Wo,
    uint16_t* __restrict__ Tfh, uint16_t* __restrict__ Tqkvh, uint16_t* __restrict__ Toh)
{
    __shared__ float t[32][33];
    const float* W; uint16_t* Th; int K, kt;
    int y = blockIdx.y;
    if (y < 32)      { W = Wf; Th = Tfh; K = 1024; kt = y; }
    else if (y < 48) { W = Wq; Th = Tqkvh; K = 512; kt = y - 32; }
    else if (y < 64) { W = Wk; Th = Tqkvh + (size_t)Dd * Dd; K = 512; kt = y - 48; }
    else if (y < 80) { W = Wv; Th = Tqkvh + (size_t)2 * Dd * Dd; K = 512; kt = y - 64; }
    else             { W = Wo; Th = Toh; K = 512; kt = y - 80; }

    int n0 = blockIdx.x * 32, k0 = kt * 32;
    int tx = threadIdx.x & 31, ty = threadIdx.x >> 5;
    #pragma unroll
    for (int i = 0; i < 4; i++) {
        int k = k0 + ty + i * 8;
        t[ty + i * 8][tx] = W[(size_t)k * Dd + n0 + tx];
    }
    __syncthreads();
    #pragma unroll
    for (int i = 0; i < 4; i++) {
        int n = n0 + ty + i * 8;
        __half h = __float2half_rn(t[tx][ty + i * 8]);
        Th[(size_t)n * K + k0 + tx] = reinterpret_cast<uint16_t&>(h);
    }
}

// ---------------------------------------------------------------------------
// fp16 single-pass HMMA GEMM: BM=128, BN=128, BK=32; 256 threads = 8 warps
// of 32x64 (wm = (wid&3)*32, wn = (wid>>2)*64). 3-stage cp.async wait<1>,
// 60 KB, 2 CTAs/SM -> 4 warps/SMSP with a full compute phase of load slack.
// Two N-segments per launch (x-split). B stored [N][K] K-major.
// ---------------------------------------------------------------------------
#define GSTR 40
#define G_PL  (128*GSTR)          // plane elems (5120)
#define G_STG (2*G_PL)            // stage elems: Ah, Bh (20 KB)

__global__ __launch_bounds__(256, 2) void gemm_tc(
    // segment 0
    const uint16_t* __restrict__ A0a, const uint16_t* __restrict__ A0b,
    const uint16_t* __restrict__ B0,
    int K0, const float* __restrict__ bias0, float scl0,
    uint16_t* __restrict__ O0, float* __restrict__ C0f,
    // segment 1
    const uint16_t* __restrict__ A1, const uint16_t* __restrict__ B1,
    int K1, const float* __restrict__ bias1, float scl1,
    uint16_t* __restrict__ O1,
    int xsplit)
{
    extern __shared__ uint16_t sm[];
    const int tid  = threadIdx.x;
    const int lane = tid & 31, wid = tid >> 5;
    const int grp  = lane >> 2, tig = lane & 3;
    const int wm = (wid & 3) * 32, wn = (wid >> 2) * 64;

    const bool s1 = ((int)blockIdx.x >= xsplit);
    const uint16_t* Aa = s1 ? A1 : A0a;
    const uint16_t* Ab = s1 ? A1 : A0b;
    const uint16_t* Bg = s1 ? B1 : B0;
    const int K = s1 ? K1 : K0;
    const float* bias = s1 ? bias1 : bias0;
    const float xscale = s1 ? scl1 : scl0;
    uint16_t* Dh = s1 ? O1 : O0;
    float* Cf = s1 ? nullptr : C0f;

    const int rowBase = blockIdx.y * 128;
    const int colBase = ((int)blockIdx.x - (s1 ? xsplit : 0)) * 128;

    const int arow = ((lane >> 3) & 1) * 8 + (lane & 7);
    const int acol = (lane >> 4) * 8;
    const int brow = (lane >> 4) * 8 + (lane & 7);
    const int bcol = ((lane >> 3) & 1) * 8;

    float acc[2][8][4];
    #pragma unroll
    for (int mt = 0; mt < 2; mt++)
        #pragma unroll
        for (int nt = 0; nt < 8; nt++)
            #pragma unroll
            for (int j = 0; j < 4; j++) acc[mt][nt][j] = 0.f;

    const int NIT = K / 32;
    const uint32_t base = smem_u32(sm);

    auto load_chunk = [&](int it) {
        uint32_t sb = base + (it % 3) * G_STG * 2;
        int k0 = it * 32;
        const uint16_t* Ap = (k0 < Dd) ? Aa : Ab;
        int ka = k0 & (Dd - 1);
        #pragma unroll
        for (int i = 0; i < 2; i++) {
            int idx = tid + i * 256;
            int r = idx >> 2, ch = idx & 3;
            size_t ga = (size_t)(rowBase + r) * Dd + ka + ch * 8;
            size_t gb = (size_t)(colBase + r) * K + k0 + ch * 8;
            uint32_t d = (r * GSTR + ch * 8) * 2;
            cpa16(sb + d,             Ap + ga);
            cpa16(sb + G_PL * 2 + d,  Bg + gb);
        }
        cpa_commit();
    };

    load_chunk(0);
    load_chunk(1);

    for (int it = 0; it < NIT; it++) {
        if (it + 1 < NIT) cpa_wait<1>(); else cpa_wait<0>();
        __syncthreads();
        if (it + 2 < NIT) load_chunk(it + 2);

        const uint16_t* Ah = sm + (it % 3) * G_STG;
        const uint16_t* Bh = Ah + G_PL;

        #pragma unroll
        for (int kk = 0; kk < 2; kk++) {
            uint32_t ah[2][4];
            #pragma unroll
            for (int mt = 0; mt < 2; mt++) {
                int off = (wm + mt * 16 + arow) * GSTR + kk * 16 + acol;
                ldsm_x4(ah[mt], smem_u32(&Ah[off]));
            }
            #pragma unroll
            for (int g = 0; g < 4; g++) {
                uint32_t bh4[4];
                int off = (wn + g * 16 + brow) * GSTR + kk * 16 + bcol;
                ldsm_x4(bh4, smem_u32(&Bh[off]));
                #pragma unroll
                for (int mt = 0; mt < 2; mt++) {
                    mma16816(acc[mt][2*g],   ah[mt], bh4);
                    mma16816(acc[mt][2*g+1], ah[mt], bh4 + 2);
                }
            }
        }
        __syncthreads();
    }

    #pragma unroll
    for (int mt = 0; mt < 2; mt++)
        #pragma unroll
        for (int nt = 0; nt < 8; nt++) {
            int row = rowBase + wm + mt * 16 + grp;
            int col = colBase + wn + nt * 8 + 2 * tig;
            float bx = bias[col], by = bias[col + 1];
            float v00 = (acc[mt][nt][0] + bx) * xscale;
            float v01 = (acc[mt][nt][1] + by) * xscale;
            float v10 = (acc[mt][nt][2] + bx) * xscale;
            float v11 = (acc[mt][nt][3] + by) * xscale;
            if (Cf) {
                *(float2*)(Cf + (size_t)row * Dd + col)       = make_float2(v00, v01);
                *(float2*)(Cf + (size_t)(row + 8) * Dd + col) = make_float2(v10, v11);
            } else {
                *(uint32_t*)&Dh[(size_t)row * Dd + col]       = pack2h(v00, v01);
                *(uint32_t*)&Dh[(size_t)(row + 8) * Dd + col] = pack2h(v10, v11);
            }
        }
}

// ---------------------------------------------------------------------------
// Flash attention (fp16 single-pass): BQ=128 (4 warps m32), BK=64, NT=32,
// 3-stage cp.async wait<1>, 2 CTAs/SM. Halved per-iter fixed costs (shfl,
// mask loads, waits, syncs) vs BK=32. Fixed-base softmax (clamp 11); masked
// p = 0 => running l == reference's sum|A|. Single fp16 output plane.
// ---------------------------------------------------------------------------
#define FSTR 72
#define F_PL  (64*FSTR)           // 4608 elems (one 64-row tile)
#define F_STG (2*F_PL)            // Kh, Vh = 9216 elems (18432 B)

__global__ __launch_bounds__(128, 2) void flash_fp16_kernel(
    const uint16_t* __restrict__ Qg, const uint16_t* __restrict__ Kg,
    const uint16_t* __restrict__ Vg, const uint32_t* __restrict__ mbits,
    uint16_t* __restrict__ Oh)
{
    extern __shared__ uint16_t sm[];
    const int tid = threadIdx.x, lane = tid & 31, w = tid >> 5;
    const int grp = lane >> 2, tig = lane & 3;
    const int b = blockIdx.y >> 3, h = blockIdx.y & 7;
    const int q0 = blockIdx.x * 128;

    const int arow = ((lane >> 3) & 1) * 8 + (lane & 7);
    const int acol = (lane >> 4) * 8;
    const int brow = (lane >> 4) * 8 + (lane & 7);
    const int bcol = ((lane >> 3) & 1) * 8;

    // ---- stage Q (128 x 64) through stage area (transient), pull A-frags ----
    {
        uint32_t base = smem_u32(sm);
        #pragma unroll
        for (int i = 0; i < 8; i++) {
            int chunk = tid + i * 128;
            int r = chunk >> 3, c = (chunk & 7) * 8;
            const size_t g = (size_t)(b * Ss + q0 + r) * Dd + h * HDIM + c;
            cpa16(base + (r * FSTR + c) * 2, Qg + g);
        }
        cpa_commit();
        cpa_wait<0>();
        __syncthreads();
    }
    uint32_t qh[2][4][4];
    #pragma unroll
    for (int mt = 0; mt < 2; mt++)
        #pragma unroll
        for (int c = 0; c < 4; c++) {
            int off = (w * 32 + mt * 16 + arow) * FSTR + c * 16 + acol;
            ldsm_x4(qh[mt][c], smem_u32(&sm[off]));
        }
    __syncthreads();

    float oacc[2][8][4];
    #pragma unroll
    for (int mt = 0; mt < 2; mt++)
        #pragma unroll
        for (int n = 0; n < 8; n++)
            #pragma unroll
            for (int j = 0; j < 4; j++) oacc[mt][n][j] = 0.f;
    float lrun[2][2] = {{0.f, 0.f}, {0.f, 0.f}};

    auto load_tile = [&](int it) {
        int k0 = it * 64;
        uint32_t base = smem_u32(sm) + (it % 3) * F_STG * 2;
        #pragma unroll
        for (int i = 0; i < 4; i++) {
            int chunk = tid + i * 128;
            int r = chunk >> 3, c = (chunk & 7) * 8;
            const size_t g = (size_t)(b * Ss + k0 + r) * Dd + h * HDIM + c;
            uint32_t d = (r * FSTR + c) * 2;
            cpa16(base + d,             Kg + g);
            cpa16(base + F_PL * 2 + d,  Vg + g);
        }
        cpa_commit();
    };

    load_tile(0);
    load_tile(1);

    const int NT = Ss / 64;
    for (int it = 0; it < NT; it++) {
        if (it + 1 < NT) cpa_wait<1>(); else cpa_wait<0>();
        __syncthreads();
        if (it + 2 < NT) load_tile(it + 2);

        const uint16_t* Kh = sm + (it % 3) * F_STG;
        const uint16_t* Vh = Kh + F_PL;
        const int k0 = it * 64;

        // ---- S = Q @ K^T (64 keys) ----
        float sacc[2][8][4];
        #pragma unroll
        for (int mt = 0; mt < 2; mt++)
            #pragma unroll
            for (int n = 0; n < 8; n++)
                #pragma unroll
                for (int j = 0; j < 4; j++) sacc[mt][n][j] = 0.f;
        #pragma unroll
        for (int c = 0; c < 4; c++) {
            #pragma unroll
            for (int g = 0; g < 4; g++) {
                uint32_t kf[4];
                int off = (g * 16 + brow) * FSTR + c * 16 + bcol;
                ldsm_x4(kf, smem_u32(&Kh[off]));
                #pragma unroll
                for (int mt = 0; mt < 2; mt++) {
                    mma16816(sacc[mt][2*g],   qh[mt][c], kf);
                    mma16816(sacc[mt][2*g+1], qh[mt][c], kf + 2);
                }
            }
        }

        // ---- masked softmax (fixed base; clamp 11) ----
        #pragma unroll
        for (int mt = 0; mt < 2; mt++)
            #pragma unroll
            for (int r = 0; r < 2; r++) {
                int qrow = q0 + w * 32 + mt * 16 + grp + r * 8;
                size_t mb = ((size_t)(b * Ss) + qrow) * (Ss / 32) + (k0 >> 5);
                uint32_t bw0 = mbits[mb], bw1 = mbits[mb + 1];
                float ps = 0.f;
                #pragma unroll
                for (int n = 0; n < 8; n++)
                    #pragma unroll
                    for (int e = 0; e < 2; e++) {
                        int col = n * 8 + 2 * tig + e;
                        uint32_t on = ((col < 32 ? bw0 : bw1) >> (col & 31)) & 1u;
                        float p = on ? __expf(fminf(sacc[mt][n][r*2+e], 11.f)) : 0.f;
                        sacc[mt][n][r*2+e] = p;
                        ps += p;
                    }
                ps += __shfl_xor_sync(0xffffffffu, ps, 1);
                ps += __shfl_xor_sync(0xffffffffu, ps, 2);
                lrun[mt][r] += ps;
            }

        // ---- O += P @ V (64-key contraction, 4 k16 steps) ----
        #pragma unroll
        for (int kc = 0; kc < 4; kc++) {
            uint32_t ph[2][4];
            #pragma unroll
            for (int mt = 0; mt < 2; mt++) {
                ph[mt][0] = pack2h(sacc[mt][2*kc][0],   sacc[mt][2*kc][1]);
                ph[mt][1] = pack2h(sacc[mt][2*kc][2],   sacc[mt][2*kc][3]);
                ph[mt][2] = pack2h(sacc[mt][2*kc+1][0], sacc[mt][2*kc+1][1]);
                ph[mt][3] = pack2h(sacc[mt][2*kc+1][2], sacc[mt][2*kc+1][3]);
            }
            #pragma unroll
            for (int c = 0; c < 4; c++) {
                uint32_t vf[4];
                int off = (kc * 16 + arow) * FSTR + c * 16 + acol;
                ldsm_x4_t(vf, smem_u32(&Vh[off]));
                #pragma unroll
                for (int mt = 0; mt < 2; mt++) {
                    mma16816(oacc[mt][2*c],   ph[mt], vf);
                    mma16816(oacc[mt][2*c+1], ph[mt], vf + 2);
                }
            }
        }
    }

    // ---- epilogue: divide by l (== sum|A|), write attn plane ----
    #pragma unroll
    for (int mt = 0; mt < 2; mt++) {
        float inv0 = (lrun[mt][0] > 0.f) ? 1.f / lrun[mt][0] : 0.f;
        float inv1 = (lrun[mt][1] > 0.f) ? 1.f / lrun[mt][1] : 0.f;
        int row0 = b * Ss + q0 + w * 32 + mt * 16 + grp;
        #pragma unroll
        for (int n = 0; n < 8; n++) {
            int col = h * HDIM + n * 8 + 2 * tig;
            *(uint32_t*)&Oh[(size_t)row0 * Dd + col] =
                pack2h(oacc[mt][n][0] * inv0, oacc[mt][n][1] * inv0);
            *(uint32_t*)&Oh[(size_t)(row0 + 8) * Dd + col] =
                pack2h(oacc[mt][n][2] * inv1, oacc[mt][n][3] * inv1);
        }
    }
}

// ---------------------------------------------------------------------------
extern "C" void kernel_launch(void* const* d_in, const int* in_sizes, int n_in,
                              void* d_out, int out_size)
{
    const float* gene = (const float*)d_in[0];
    const float* expr = (const float*)d_in[1];
    const float* Mm   = (const float*)d_in[2];
    const float* Wf   = (const float*)d_in[3];
    const float* bf   = (const float*)d_in[4];
    const float* Wq   = (const float*)d_in[5];
    const float* bq   = (const float*)d_in[6];
    const float* Wk   = (const float*)d_in[7];
    const float* bk   = (const float*)d_in[8];
    const float* Wv   = (const float*)d_in[9];
    const float* bv   = (const float*)d_in[10];
    const float* Wo   = (const float*)d_in[11];
    const float* bo   = (const float*)d_in[12];
    float* out = (float*)d_out;

    uint16_t *geneh, *exprh, *fush, *qh, *kh, *vh, *ath;
    uint16_t *wtfh, *wtqkvh, *wtoh;
    uint32_t* mbits;
    cudaGetSymbolAddress((void**)&geneh, g_gene_h);
    cudaGetSymbolAddress((void**)&exprh, g_expr_h);
    cudaGetSymbolAddress((void**)&fush,  g_fus_h);
    cudaGetSymbolAddress((void**)&qh,    g_q_h);
    cudaGetSymbolAddress((void**)&kh,    g_k_h);
    cudaGetSymbolAddress((void**)&vh,    g_v_h);
    cudaGetSymbolAddress((void**)&ath,   g_at_h);
    cudaGetSymbolAddress((void**)&wtfh,  g_wtf_h);
    cudaGetSymbolAddress((void**)&wtqkvh, g_wtqkv_h);
    cudaGetSymbolAddress((void**)&wtoh,  g_wto_h);
    cudaGetSymbolAddress((void**)&mbits, g_mbits);

    const uint16_t* wtqh = wtqkvh;
    const uint16_t* wtkh = wtqkvh + (size_t)Dd * Dd;
    const uint16_t* wtvh = wtqkvh + (size_t)2 * Dd * Dd;

    const int SMG = 3 * G_STG * 2;                  // 61440 B
    const int SMF = 3 * F_STG * 2;                  // 55296 B
    cudaFuncSetAttribute(gemm_tc, cudaFuncAttributeMaxDynamicSharedMemorySize, SMG);
    cudaFuncSetAttribute(flash_fp16_kernel, cudaFuncAttributeMaxDynamicSharedMemorySize, SMF);

    const int NE = Bb * Ss * Dd;
    maskbits_kernel<<<(Bb * Ss * Ss) / 256, 256>>>(Mm, mbits);
    conv_kernel<<<dim3(NE / 1024, 2), 256>>>(gene, geneh, expr, exprh);
    transpose_all_kernel<<<dim3(16, 96), 256>>>(Wf, Wq, Wk, Wv, Wo, wtfh, wtqkvh, wtoh);

    const int MR = Bb * Ss;                        // 4096
    // launch A: fused (seg0, K=1024) || V (seg1, K=512)
    gemm_tc<<<dim3(8, MR / 128), 256, SMG>>>(
        geneh, exprh, wtfh, 2 * Dd, bf, 1.f, fush, nullptr,
        exprh, wtvh, Dd, bv, 1.f, vh,
        4);
    // launch B: Q (seg0, xSCALE) || K (seg1)
    gemm_tc<<<dim3(8, MR / 128), 256, SMG>>>(
        fush, fush, wtqh, Dd, bq, SCALE, qh, nullptr,
        fush, wtkh, Dd, bk, 1.f, kh,
        4);
    // flash attention
    flash_fp16_kernel<<<dim3(Ss / 128, Bb * Hh), 128, SMF>>>(
        qh, kh, vh, mbits, ath);
    // out projection -> f32 d_out
    gemm_tc<<<dim3(4, MR / 128), 256, SMG>>>(
        ath, ath, wtoh, Dd, bo, 1.f, nullptr, out,
        ath, wtoh, Dd, bo, 1.f, nullptr,
        8);
}